// round 14
// baseline (speedup 1.0000x reference)
#include <cuda_runtime.h>
#include <cuda_bf16.h>
#include <cstdint>

#define N_NODES 50000
#define DFEAT 128
#define MAX_E 800000
#define SCAN_BLK 1024
#define NSCAN ((N_NODES + SCAN_BLK - 1) / SCAN_BLK)   // 49

// ---- scratch (static device globals: allocation-free) ----
__device__ float g_hs[N_NODES * DFEAT];    // (X@W) * dinv[row]
__device__ float g_buf[N_NODES * DFEAT];   // layer-1 output / layer-2 input
__device__ float g_dinv[N_NODES];
__device__ int   g_cnt[N_NODES];
__device__ int   g_cursor[N_NODES];
__device__ int   g_rowptr[N_NODES + 1];
__device__ int   g_csr[MAX_E];
__device__ int   g_bsum[64];
__device__ __nv_bfloat16 g_wh[DFEAT * DFEAT];    // W1^T hi  [n][k]
__device__ __nv_bfloat16 g_wl[DFEAT * DFEAT];    // W1^T lo
__device__ __nv_bfloat16 g_wh2[DFEAT * DFEAT];   // W2^T hi
__device__ __nv_bfloat16 g_wl2[DFEAT * DFEAT];   // W2^T lo

// ---------------- graph build ----------------
__global__ void zero_counters() {
    int i = blockIdx.x * blockDim.x + threadIdx.x;
    if (i < N_NODES) { g_cnt[i] = 0; g_cursor[i] = 0; }
}
__global__ void count_deg(const int* __restrict__ dst, int E) {
    int e = blockIdx.x * blockDim.x + threadIdx.x;
    if (e < E) atomicAdd(&g_cnt[dst[e]], 1);
}

// phase A: per-block local exclusive scan + block totals
__global__ void scan_local() {
    __shared__ int wsum[32];
    int t = threadIdx.x;
    int i = blockIdx.x * SCAN_BLK + t;
    int v = (i < N_NODES) ? g_cnt[i] : 0;
    int x = v;
#pragma unroll
    for (int off = 1; off < 32; off <<= 1) {
        int y = __shfl_up_sync(0xFFFFFFFFu, x, off);
        if ((t & 31) >= off) x += y;
    }
    if ((t & 31) == 31) wsum[t >> 5] = x;
    __syncthreads();
    if (t < 32) {
        int w = wsum[t];
#pragma unroll
        for (int off = 1; off < 32; off <<= 1) {
            int y = __shfl_up_sync(0xFFFFFFFFu, w, off);
            if (t >= off) w += y;
        }
        wsum[t] = w;
    }
    __syncthreads();
    int base = (t >= 32) ? wsum[(t >> 5) - 1] : 0;
    if (i < N_NODES) g_rowptr[i] = base + x - v;           // local exclusive prefix
    if (t == SCAN_BLK - 1) g_bsum[blockIdx.x] = base + x;  // block total
}
// phase B (merged): add block offsets (computed inline), dinv, sentinel
__global__ void scan_apply(int E) {
    __shared__ int s_off;
    int i = blockIdx.x * blockDim.x + threadIdx.x;
    int blk = (blockIdx.x * blockDim.x) / SCAN_BLK;        // scan-block of this range
    if (threadIdx.x == 0) {
        int o = 0;
        for (int j = 0; j < blk; j++) o += g_bsum[j];
        s_off = o;
    }
    __syncthreads();
    if (i < N_NODES) {
        g_rowptr[i] += s_off;
        g_dinv[i] = rsqrtf((float)g_cnt[i] + 1.0f);
    }
    if (i == 0) g_rowptr[N_NODES] = E;
}

__global__ void fill_csr(const int* __restrict__ src,
                         const int* __restrict__ dst, int E) {
    int e = blockIdx.x * blockDim.x + threadIdx.x;
    if (e < E) {
        int d = dst[e];
        int pos = atomicAdd(&g_cursor[d], 1);
        g_csr[g_rowptr[d] + pos] = src[e];
    }
}

// ---------------- both W -> transposed bf16 hi/lo (one launch) ----------------
__global__ void wconvert2(const float* __restrict__ W1, const float* __restrict__ W2) {
    int i = blockIdx.x * blockDim.x + threadIdx.x;
    if (i < DFEAT * DFEAT) {
        int k = i >> 7, n = i & 127;
        float w = W1[i];
        __nv_bfloat16 h = __float2bfloat16_rn(w);
        g_wh[n * DFEAT + k] = h;
        g_wl[n * DFEAT + k] = __float2bfloat16_rn(w - __bfloat162float(h));
        float w2 = W2[i];
        __nv_bfloat16 h2 = __float2bfloat16_rn(w2);
        g_wh2[n * DFEAT + k] = h2;
        g_wl2[n * DFEAT + k] = __float2bfloat16_rn(w2 - __bfloat162float(h2));
    }
}

// bf16x2 pack: low half = a, high half = b
__device__ __forceinline__ uint32_t pack_bf2(float a, float b) {
    uint32_t r;
    asm("cvt.rn.bf16x2.f32 %0, %1, %2;" : "=r"(r) : "f"(b), "f"(a));
    return r;
}

#define MMA(ac, a0, a1, a2, a3, b0, b1)                                      \
    asm volatile("mma.sync.aligned.m16n8k16.row.col.f32.bf16.bf16.f32 "      \
                 "{%0,%1,%2,%3}, {%4,%5,%6,%7}, {%8,%9}, {%0,%1,%2,%3};"     \
                 : "+f"(ac[0]), "+f"(ac[1]), "+f"(ac[2]), "+f"(ac[3])        \
                 : "r"(a0), "r"(a1), "r"(a2), "r"(a3), "r"(b0), "r"(b1))

// ---- GEMM: out[row] = (X[row] @ W) * dinv[row]  via mma.sync bf16x3 split ----
__global__ void __launch_bounds__(256, 2)
gemm_mma(const float* __restrict__ X,
         const __nv_bfloat16* __restrict__ wh,
         const __nv_bfloat16* __restrict__ wl,
         float* __restrict__ out, int nrows) {
    int lane = threadIdx.x & 31, wid = threadIdx.x >> 5;
    int gid = lane >> 2, tig = lane & 3;
    int wm = wid >> 1, wn = wid & 1;
    int row0 = blockIdx.x * 128 + wm * 32;
    int n0w = wn * 64;

    float acc[2][8][4];
#pragma unroll
    for (int mt = 0; mt < 2; mt++)
#pragma unroll
        for (int nt = 0; nt < 8; nt++)
#pragma unroll
            for (int q = 0; q < 4; q++) acc[mt][nt][q] = 0.f;

#pragma unroll
    for (int ks = 0; ks < 8; ks++) {
        int kb = ks * 16;
        uint32_t ah[2][4], al[2][4];
#pragma unroll
        for (int mt = 0; mt < 2; mt++) {
            int rbase = row0 + mt * 16 + gid;
#pragma unroll
            for (int q = 0; q < 4; q++) {
                int r = rbase + (q & 1) * 8;
                int c = kb + 2 * tig + (q >> 1) * 8;
                float2 v = make_float2(0.f, 0.f);
                if (r < nrows) v = *(const float2*)(X + (size_t)r * DFEAT + c);
                uint32_t h = pack_bf2(v.x, v.y);
                float hx = __uint_as_float(h << 16);
                float hy = __uint_as_float(h & 0xFFFF0000u);
                al[mt][q] = pack_bf2(v.x - hx, v.y - hy);
                ah[mt][q] = h;
            }
        }
#pragma unroll
        for (int nt = 0; nt < 8; nt++) {
            int nc = n0w + nt * 8 + gid;
            const uint32_t* ph = (const uint32_t*)(wh + nc * DFEAT + kb + 2 * tig);
            const uint32_t* pl = (const uint32_t*)(wl + nc * DFEAT + kb + 2 * tig);
            uint32_t bh0 = ph[0], bh1 = ph[4];
            uint32_t bl0 = pl[0], bl1 = pl[4];
#pragma unroll
            for (int mt = 0; mt < 2; mt++) {
                MMA(acc[mt][nt], ah[mt][0], ah[mt][1], ah[mt][2], ah[mt][3], bh0, bh1);
                MMA(acc[mt][nt], ah[mt][0], ah[mt][1], ah[mt][2], ah[mt][3], bl0, bl1);
                MMA(acc[mt][nt], al[mt][0], al[mt][1], al[mt][2], al[mt][3], bh0, bh1);
            }
        }
    }

#pragma unroll
    for (int mt = 0; mt < 2; mt++) {
        int r = row0 + mt * 16 + gid;
        float d0 = (r < nrows) ? g_dinv[r] : 0.f;
        float d1 = (r + 8 < nrows) ? g_dinv[r + 8] : 0.f;
#pragma unroll
        for (int nt = 0; nt < 8; nt++) {
            int c = n0w + nt * 8 + 2 * tig;
            if (r < nrows)
                *(float2*)(out + (size_t)r * DFEAT + c) =
                    make_float2(acc[mt][nt][0] * d0, acc[mt][nt][1] * d0);
            if (r + 8 < nrows)
                *(float2*)(out + (size_t)(r + 8) * DFEAT + c) =
                    make_float2(acc[mt][nt][2] * d1, acc[mt][nt][3] * d1);
        }
    }
}

// ------ aggregation ------
__global__ void aggregate_relu(const float* __restrict__ hs,
                               const float* __restrict__ bias,
                               float* __restrict__ out) {
    int gw = (blockIdx.x * blockDim.x + threadIdx.x) >> 5;
    int lane = threadIdx.x & 31;
    if (gw >= N_NODES) return;
    const float4* hs4 = (const float4*)hs;
    float4 acc = hs4[(size_t)gw * 32 + lane];
    int e0 = g_rowptr[gw], e1 = g_rowptr[gw + 1];
    for (int e = e0; e < e1; e++) {
        int s = g_csr[e];
        float4 v = hs4[(size_t)s * 32 + lane];
        acc.x += v.x; acc.y += v.y; acc.z += v.z; acc.w += v.w;
    }
    float d = g_dinv[gw];
    float4 b = ((const float4*)bias)[lane];
    float4 r;
    r.x = fmaxf(fmaf(acc.x, d, b.x), 0.f);
    r.y = fmaxf(fmaf(acc.y, d, b.y), 0.f);
    r.z = fmaxf(fmaf(acc.z, d, b.z), 0.f);
    r.w = fmaxf(fmaf(acc.w, d, b.w), 0.f);
    ((float4*)out)[(size_t)gw * 32 + lane] = r;
}

__global__ void aggregate_final(const float* __restrict__ hs,
                                const float* __restrict__ bias,
                                const float* __restrict__ Wl,
                                const float* __restrict__ bl,
                                float* __restrict__ out) {
    int gw = (blockIdx.x * blockDim.x + threadIdx.x) >> 5;
    int lane = threadIdx.x & 31;
    if (gw >= N_NODES) return;
    const float4* hs4 = (const float4*)hs;
    float4 acc = hs4[(size_t)gw * 32 + lane];
    int e0 = g_rowptr[gw], e1 = g_rowptr[gw + 1];
    for (int e = e0; e < e1; e++) {
        int s = g_csr[e];
        float4 v = hs4[(size_t)s * 32 + lane];
        acc.x += v.x; acc.y += v.y; acc.z += v.z; acc.w += v.w;
    }
    float d = g_dinv[gw];
    float4 b = ((const float4*)bias)[lane];
    float4 r;
    r.x = fmaxf(fmaf(acc.x, d, b.x), 0.f);
    r.y = fmaxf(fmaf(acc.y, d, b.y), 0.f);
    r.z = fmaxf(fmaf(acc.z, d, b.z), 0.f);
    r.w = fmaxf(fmaf(acc.w, d, b.w), 0.f);
    float4 wl = ((const float4*)Wl)[lane];
    float dot = r.x * wl.x + r.y * wl.y + r.z * wl.z + r.w * wl.w;
#pragma unroll
    for (int off = 16; off; off >>= 1)
        dot += __shfl_xor_sync(0xFFFFFFFFu, dot, off);
    if (lane == 0) out[gw] = dot + bl[0];
}

// ---------------- launch ----------------
extern "C" void kernel_launch(void* const* d_in, const int* in_sizes, int n_in,
                              void* d_out, int out_size) {
    const float* x  = (const float*)d_in[0];
    const int*   ei = (const int*)d_in[1];    // int32 (JAX x64 disabled)
    const float* W1 = (const float*)d_in[2];
    const float* b1 = (const float*)d_in[3];
    const float* W2 = (const float*)d_in[4];
    const float* b2 = (const float*)d_in[5];
    const float* Wl = (const float*)d_in[6];
    const float* bl = (const float*)d_in[7];
    float* out = (float*)d_out;

    int E = in_sizes[1] / 2;
    const int* src = ei;
    const int* dst = ei + E;

    void *p_hs, *p_buf, *p_wh, *p_wl, *p_wh2, *p_wl2;
    cudaGetSymbolAddress(&p_hs, g_hs);
    cudaGetSymbolAddress(&p_buf, g_buf);
    cudaGetSymbolAddress(&p_wh, g_wh);
    cudaGetSymbolAddress(&p_wl, g_wl);
    cudaGetSymbolAddress(&p_wh2, g_wh2);
    cudaGetSymbolAddress(&p_wl2, g_wl2);
    float* hs  = (float*)p_hs;
    float* buf = (float*)p_buf;
    __nv_bfloat16* wh  = (__nv_bfloat16*)p_wh;
    __nv_bfloat16* wl  = (__nv_bfloat16*)p_wl;
    __nv_bfloat16* wh2 = (__nv_bfloat16*)p_wh2;
    __nv_bfloat16* wl2 = (__nv_bfloat16*)p_wl2;

    static cudaStream_t s2 = []() {
        cudaStream_t s; cudaStreamCreateWithFlags(&s, cudaStreamNonBlocking); return s;
    }();
    static cudaEvent_t evF = []() {
        cudaEvent_t e; cudaEventCreateWithFlags(&e, cudaEventDisableTiming); return e;
    }();
    static cudaEvent_t evW = []() {
        cudaEvent_t e; cudaEventCreateWithFlags(&e, cudaEventDisableTiming); return e;
    }();
    static cudaEvent_t evS = []() {
        cudaEvent_t e; cudaEventCreateWithFlags(&e, cudaEventDisableTiming); return e;
    }();
    static cudaEvent_t evJ = []() {
        cudaEvent_t e; cudaEventCreateWithFlags(&e, cudaEventDisableTiming); return e;
    }();

    int gemm_grid = (N_NODES + 127) / 128;   // 391
    int agg_grid  = (N_NODES + 7) / 8;

    // s2: wconvert2 at t=0, overlapping the main-stream prefix
    cudaEventRecord(evF, 0);
    cudaStreamWaitEvent(s2, evF, 0);
    wconvert2<<<(DFEAT * DFEAT + 255) / 256, 256, 0, s2>>>(W1, W2);
    cudaEventRecord(evW, s2);

    // main prefix: degree/scan
    zero_counters<<<(N_NODES + 255) / 256, 256>>>();
    count_deg<<<(E + 255) / 256, 256>>>(dst, E);
    scan_local<<<NSCAN, SCAN_BLK>>>();
    scan_apply<<<(N_NODES + 255) / 256, 256>>>(E);
    cudaEventRecord(evS, 0);

    // gemm1 on main (needs scan [same stream] + wconvert [evW])
    cudaStreamWaitEvent(0, evW, 0);
    gemm_mma<<<gemm_grid, 256>>>(x, wh, wl, hs, N_NODES);   // 6th launch -> ncu

    // fill_csr on s2 (needs scan via evS); overlaps gemm1
    cudaStreamWaitEvent(s2, evS, 0);
    fill_csr<<<(E + 255) / 256, 256, 0, s2>>>(src, dst, E);
    cudaEventRecord(evJ, s2);

    // join: agg1 needs CSR
    cudaStreamWaitEvent(0, evJ, 0);
    aggregate_relu<<<agg_grid, 256>>>(hs, b1, buf);
    gemm_mma<<<gemm_grid, 256>>>(buf, wh2, wl2, hs, N_NODES);
    aggregate_final<<<agg_grid, 256>>>(hs, b2, Wl, bl, out);
}

// round 17
// speedup vs baseline: 1.2559x; 1.2559x over previous
#include <cuda_runtime.h>
#include <cuda_bf16.h>
#include <cstdint>

#define N_NODES 50000
#define DFEAT 128
#define MAX_E 800000
#define SCAN_BLK 1024
#define NSCAN ((N_NODES + SCAN_BLK - 1) / SCAN_BLK)   // 49

// ---- scratch (static device globals: allocation-free) ----
__device__ float g_hs[N_NODES * DFEAT];    // (X@W) * dinv[row]
__device__ float g_buf[N_NODES * DFEAT];   // layer-1 output / layer-2 input
__device__ float g_dinv[N_NODES];
__device__ int   g_cnt[N_NODES];
__device__ int   g_cursor[N_NODES];
__device__ int   g_rowptr[N_NODES + 1];
__device__ int   g_csr[MAX_E];
__device__ int   g_bsum[64];
// B fragments packed per (n, kstep, tig): {bh0, bh1, bl0, bl1}
__device__ uint4 g_wpk1[DFEAT * 8 * 4];   // 4096 uint4 = 64KB
__device__ uint4 g_wpk2[DFEAT * 8 * 4];

// ---------------- graph build ----------------
__global__ void count_deg(const int* __restrict__ dst, int E) {
    int e = blockIdx.x * blockDim.x + threadIdx.x;
    if (e < E) atomicAdd(&g_cnt[dst[e]], 1);
}

// phase A: per-block local exclusive scan + block totals
__global__ void scan_local() {
    __shared__ int wsum[32];
    int t = threadIdx.x;
    int i = blockIdx.x * SCAN_BLK + t;
    int v = (i < N_NODES) ? g_cnt[i] : 0;
    int x = v;
#pragma unroll
    for (int off = 1; off < 32; off <<= 1) {
        int y = __shfl_up_sync(0xFFFFFFFFu, x, off);
        if ((t & 31) >= off) x += y;
    }
    if ((t & 31) == 31) wsum[t >> 5] = x;
    __syncthreads();
    if (t < 32) {
        int w = wsum[t];
#pragma unroll
        for (int off = 1; off < 32; off <<= 1) {
            int y = __shfl_up_sync(0xFFFFFFFFu, w, off);
            if (t >= off) w += y;
        }
        wsum[t] = w;
    }
    __syncthreads();
    int base = (t >= 32) ? wsum[(t >> 5) - 1] : 0;
    if (i < N_NODES) g_rowptr[i] = base + x - v;
    if (t == SCAN_BLK - 1) g_bsum[blockIdx.x] = base + x;
}
// phase B: add block offsets (inline prefix over 49 sums), dinv, sentinel
__global__ void scan_apply(int E) {
    __shared__ int s_off;
    int i = blockIdx.x * blockDim.x + threadIdx.x;
    int blk = (blockIdx.x * blockDim.x) / SCAN_BLK;
    if (threadIdx.x == 0) {
        int o = 0;
        for (int j = 0; j < blk; j++) o += g_bsum[j];
        s_off = o;
    }
    __syncthreads();
    if (i < N_NODES) {
        g_rowptr[i] += s_off;
        g_dinv[i] = rsqrtf((float)g_cnt[i] + 1.0f);
    }
    if (i == 0) g_rowptr[N_NODES] = E;
}

__global__ void fill_csr(const int* __restrict__ src,
                         const int* __restrict__ dst, int E) {
    int e = blockIdx.x * blockDim.x + threadIdx.x;
    if (e < E) {
        int d = dst[e];
        int pos = atomicAdd(&g_cursor[d], 1);
        g_csr[g_rowptr[d] + pos] = src[e];
    }
}

// ------ W -> packed bf16 hi/lo fragment layout (one launch, both weights) ------
// slot layout per uint4 (8 bf16): [h@k0, h@k1, h@k8, h@k9, l@k0, l@k1, l@k8, l@k9]
// where k0 = 16*ks + 2*tig.
__global__ void wconvert2(const float* __restrict__ W1, const float* __restrict__ W2) {
    int i = blockIdx.x * blockDim.x + threadIdx.x;
    if (i < DFEAT * DFEAT) {
        int k = i >> 7, n = i & 127;       // W stored [k][n]
        int ks = k >> 4, pos = k & 15;
        int tig = (pos & 7) >> 1;
        int slot = (((n * 8 + ks) * 4 + tig) << 3) + ((pos >= 8) ? 2 : 0) + (k & 1);
        {
            float w = W1[i];
            __nv_bfloat16 h = __float2bfloat16_rn(w);
            ((__nv_bfloat16*)g_wpk1)[slot]     = h;
            ((__nv_bfloat16*)g_wpk1)[slot + 4] = __float2bfloat16_rn(w - __bfloat162float(h));
        }
        {
            float w = W2[i];
            __nv_bfloat16 h = __float2bfloat16_rn(w);
            ((__nv_bfloat16*)g_wpk2)[slot]     = h;
            ((__nv_bfloat16*)g_wpk2)[slot + 4] = __float2bfloat16_rn(w - __bfloat162float(h));
        }
    }
}

// bf16x2 pack: low half = a, high half = b
__device__ __forceinline__ uint32_t pack_bf2(float a, float b) {
    uint32_t r;
    asm("cvt.rn.bf16x2.f32 %0, %1, %2;" : "=r"(r) : "f"(b), "f"(a));
    return r;
}

#define MMA(ac, a0, a1, a2, a3, b0, b1)                                      \
    asm volatile("mma.sync.aligned.m16n8k16.row.col.f32.bf16.bf16.f32 "      \
                 "{%0,%1,%2,%3}, {%4,%5,%6,%7}, {%8,%9}, {%0,%1,%2,%3};"     \
                 : "+f"(ac[0]), "+f"(ac[1]), "+f"(ac[2]), "+f"(ac[3])        \
                 : "r"(a0), "r"(a1), "r"(a2), "r"(a3), "r"(b0), "r"(b1))

// ---- GEMM: out[row] = (X[row] @ W) * dinv[row]  via mma.sync bf16x3 split ----
__global__ void __launch_bounds__(256, 2)
gemm_mma(const float* __restrict__ X,
         const uint4* __restrict__ wpk,
         float* __restrict__ out, int nrows) {
    int lane = threadIdx.x & 31, wid = threadIdx.x >> 5;
    int gid = lane >> 2, tig = lane & 3;
    int wm = wid >> 1, wn = wid & 1;
    int row0 = blockIdx.x * 128 + wm * 32;
    int n0w = wn * 64;

    float acc[2][8][4];
#pragma unroll
    for (int mt = 0; mt < 2; mt++)
#pragma unroll
        for (int nt = 0; nt < 8; nt++)
#pragma unroll
            for (int q = 0; q < 4; q++) acc[mt][nt][q] = 0.f;

#pragma unroll
    for (int ks = 0; ks < 8; ks++) {
        int kb = ks * 16;
        uint32_t ah[2][4], al[2][4];
#pragma unroll
        for (int mt = 0; mt < 2; mt++) {
            int rbase = row0 + mt * 16 + gid;
#pragma unroll
            for (int q = 0; q < 4; q++) {
                int r = rbase + (q & 1) * 8;
                int c = kb + 2 * tig + (q >> 1) * 8;
                float2 v = make_float2(0.f, 0.f);
                if (r < nrows) v = *(const float2*)(X + (size_t)r * DFEAT + c);
                uint32_t h = pack_bf2(v.x, v.y);
                float hx = __uint_as_float(h << 16);
                float hy = __uint_as_float(h & 0xFFFF0000u);
                al[mt][q] = pack_bf2(v.x - hx, v.y - hy);
                ah[mt][q] = h;
            }
        }
#pragma unroll
        for (int nt = 0; nt < 8; nt++) {
            int nc = n0w + nt * 8 + gid;
            uint4 b = wpk[((nc * 8 + ks) << 2) + tig];   // {bh0,bh1,bl0,bl1}
#pragma unroll
            for (int mt = 0; mt < 2; mt++) {
                MMA(acc[mt][nt], ah[mt][0], ah[mt][1], ah[mt][2], ah[mt][3], b.x, b.y);
                MMA(acc[mt][nt], ah[mt][0], ah[mt][1], ah[mt][2], ah[mt][3], b.z, b.w);
                MMA(acc[mt][nt], al[mt][0], al[mt][1], al[mt][2], al[mt][3], b.x, b.y);
            }
        }
    }

#pragma unroll
    for (int mt = 0; mt < 2; mt++) {
        int r = row0 + mt * 16 + gid;
        float d0 = (r < nrows) ? g_dinv[r] : 0.f;
        float d1 = (r + 8 < nrows) ? g_dinv[r + 8] : 0.f;
#pragma unroll
        for (int nt = 0; nt < 8; nt++) {
            int c = n0w + nt * 8 + 2 * tig;
            if (r < nrows)
                *(float2*)(out + (size_t)r * DFEAT + c) =
                    make_float2(acc[mt][nt][0] * d0, acc[mt][nt][1] * d0);
            if (r + 8 < nrows)
                *(float2*)(out + (size_t)(r + 8) * DFEAT + c) =
                    make_float2(acc[mt][nt][2] * d1, acc[mt][nt][3] * d1);
        }
    }
}

// ------ aggregation ------
__global__ void aggregate_relu(const float* __restrict__ hs,
                               const float* __restrict__ bias,
                               float* __restrict__ out) {
    int gw = (blockIdx.x * blockDim.x + threadIdx.x) >> 5;
    int lane = threadIdx.x & 31;
    if (gw >= N_NODES) return;
    const float4* hs4 = (const float4*)hs;
    float4 acc = hs4[(size_t)gw * 32 + lane];
    int e0 = g_rowptr[gw], e1 = g_rowptr[gw + 1];
    for (int e = e0; e < e1; e++) {
        int s = g_csr[e];
        float4 v = hs4[(size_t)s * 32 + lane];
        acc.x += v.x; acc.y += v.y; acc.z += v.z; acc.w += v.w;
    }
    float d = g_dinv[gw];
    float4 b = ((const float4*)bias)[lane];
    float4 r;
    r.x = fmaxf(fmaf(acc.x, d, b.x), 0.f);
    r.y = fmaxf(fmaf(acc.y, d, b.y), 0.f);
    r.z = fmaxf(fmaf(acc.z, d, b.z), 0.f);
    r.w = fmaxf(fmaf(acc.w, d, b.w), 0.f);
    ((float4*)out)[(size_t)gw * 32 + lane] = r;
}

__global__ void aggregate_final(const float* __restrict__ hs,
                                const float* __restrict__ bias,
                                const float* __restrict__ Wl,
                                const float* __restrict__ bl,
                                float* __restrict__ out) {
    int gw = (blockIdx.x * blockDim.x + threadIdx.x) >> 5;
    int lane = threadIdx.x & 31;
    if (gw >= N_NODES) return;
    const float4* hs4 = (const float4*)hs;
    float4 acc = hs4[(size_t)gw * 32 + lane];
    int e0 = g_rowptr[gw], e1 = g_rowptr[gw + 1];
    for (int e = e0; e < e1; e++) {
        int s = g_csr[e];
        float4 v = hs4[(size_t)s * 32 + lane];
        acc.x += v.x; acc.y += v.y; acc.z += v.z; acc.w += v.w;
    }
    float d = g_dinv[gw];
    float4 b = ((const float4*)bias)[lane];
    float4 r;
    r.x = fmaxf(fmaf(acc.x, d, b.x), 0.f);
    r.y = fmaxf(fmaf(acc.y, d, b.y), 0.f);
    r.z = fmaxf(fmaf(acc.z, d, b.z), 0.f);
    r.w = fmaxf(fmaf(acc.w, d, b.w), 0.f);
    float4 wl = ((const float4*)Wl)[lane];
    float dot = r.x * wl.x + r.y * wl.y + r.z * wl.z + r.w * wl.w;
#pragma unroll
    for (int off = 16; off; off >>= 1)
        dot += __shfl_xor_sync(0xFFFFFFFFu, dot, off);
    if (lane == 0) out[gw] = dot + bl[0];
}

// ---------------- launch ----------------
extern "C" void kernel_launch(void* const* d_in, const int* in_sizes, int n_in,
                              void* d_out, int out_size) {
    const float* x  = (const float*)d_in[0];
    const int*   ei = (const int*)d_in[1];    // int32 (JAX x64 disabled)
    const float* W1 = (const float*)d_in[2];
    const float* b1 = (const float*)d_in[3];
    const float* W2 = (const float*)d_in[4];
    const float* b2 = (const float*)d_in[5];
    const float* Wl = (const float*)d_in[6];
    const float* bl = (const float*)d_in[7];
    float* out = (float*)d_out;

    int E = in_sizes[1] / 2;
    const int* src = ei;
    const int* dst = ei + E;

    void *p_hs, *p_buf, *p_w1, *p_w2, *p_cnt, *p_cur;
    cudaGetSymbolAddress(&p_hs, g_hs);
    cudaGetSymbolAddress(&p_buf, g_buf);
    cudaGetSymbolAddress(&p_w1, g_wpk1);
    cudaGetSymbolAddress(&p_w2, g_wpk2);
    cudaGetSymbolAddress(&p_cnt, g_cnt);
    cudaGetSymbolAddress(&p_cur, g_cursor);
    float* hs  = (float*)p_hs;
    float* buf = (float*)p_buf;
    const uint4* wpk1 = (const uint4*)p_w1;
    const uint4* wpk2 = (const uint4*)p_w2;

    static cudaStream_t s2 = []() {
        cudaStream_t s; cudaStreamCreateWithFlags(&s, cudaStreamNonBlocking); return s;
    }();
    static cudaEvent_t evF = []() {
        cudaEvent_t e; cudaEventCreateWithFlags(&e, cudaEventDisableTiming); return e;
    }();
    static cudaEvent_t evW = []() {
        cudaEvent_t e; cudaEventCreateWithFlags(&e, cudaEventDisableTiming); return e;
    }();
    static cudaEvent_t evS = []() {
        cudaEvent_t e; cudaEventCreateWithFlags(&e, cudaEventDisableTiming); return e;
    }();
    static cudaEvent_t evJ = []() {
        cudaEvent_t e; cudaEventCreateWithFlags(&e, cudaEventDisableTiming); return e;
    }();

    int gemm_grid = (N_NODES + 127) / 128;   // 391
    int agg_grid  = (N_NODES + 7) / 8;

    // s2: wconvert2 at t=0, overlapping the main-stream prefix
    cudaEventRecord(evF, 0);
    cudaStreamWaitEvent(s2, evF, 0);
    wconvert2<<<(DFEAT * DFEAT + 255) / 256, 256, 0, s2>>>(W1, W2);
    cudaEventRecord(evW, s2);

    // main prefix: zero (memset nodes) + degree/scan
    cudaMemsetAsync(p_cnt, 0, N_NODES * sizeof(int), 0);
    cudaMemsetAsync(p_cur, 0, N_NODES * sizeof(int), 0);
    count_deg<<<(E + 255) / 256, 256>>>(dst, E);
    scan_local<<<NSCAN, SCAN_BLK>>>();
    scan_apply<<<(N_NODES + 255) / 256, 256>>>(E);
    cudaEventRecord(evS, 0);

    // gemm1 on main (needs scan [same stream] + wconvert [evW])
    cudaStreamWaitEvent(0, evW, 0);
    gemm_mma<<<gemm_grid, 256>>>(x, wpk1, hs, N_NODES);

    // fill_csr on s2 (needs scan via evS); overlaps gemm1
    cudaStreamWaitEvent(s2, evS, 0);
    fill_csr<<<(E + 255) / 256, 256, 0, s2>>>(src, dst, E);
    cudaEventRecord(evJ, s2);

    // join: agg1 needs CSR
    cudaStreamWaitEvent(0, evJ, 0);
    aggregate_relu<<<agg_grid, 256>>>(hs, b1, buf);
    gemm_mma<<<gemm_grid, 256>>>(buf, wpk2, hs, N_NODES);
    aggregate_final<<<agg_grid, 256>>>(hs, b2, Wl, bl, out);
}